// round 9
// baseline (speedup 1.0000x reference)
#include <cuda_runtime.h>

#define NQ      14
#define DIM     (1 << NQ)       // 16384 amplitudes
#define HALF    (DIM / 2)       // 8192 packed u64 per plane
#define NL      8
#define NGATES  ((NL + 1) * NQ) // 126 single-qubit gates
#define THREADS 512

typedef unsigned long long u64;

// XOR swizzle on u64-plane index; all passes use the same mapping.
__device__ __forceinline__ int phys64(int p) { return p ^ ((p >> 4) & 15); }

__device__ __forceinline__ u64 pk2(float lo, float hi) {
    u64 r; asm("mov.b64 %0, {%1,%2};" : "=l"(r) : "f"(lo), "f"(hi)); return r;
}
__device__ __forceinline__ void upk2(u64 v, float& lo, float& hi) {
    asm("mov.b64 {%0,%1}, %2;" : "=f"(lo), "=f"(hi) : "l"(v));
}
__device__ __forceinline__ u64 swap2(u64 v) {
    float lo, hi; upk2(v, lo, hi); return pk2(hi, lo);
}
__device__ __forceinline__ u64 fma2(u64 a, u64 b, u64 c) {
    u64 d; asm("fma.rn.f32x2 %0, %1, %2, %3;" : "=l"(d) : "l"(a), "l"(b), "l"(c));
    return d;
}
__device__ __forceinline__ u64 mul2(u64 a, u64 b) {
    u64 d; asm("mul.rn.f32x2 %0, %1, %2;" : "=l"(d) : "l"(a), "l"(b));
    return d;
}

// Gate matrix structure (U = [[pm*cx, pm*(-i sx)],[pp*(-i sx), pp*cx]]):
//   u00 = (a, b)   u01 = (c, d)
//   u10 = (-c, d)  u11 = (a, -b)
// with a=pr*cx, b=pii*cx, c=pii*sx, d=-pr*sx.

// Broadcast gate: butterfly partners are distinct packed elements (bit BIT of j).
template<int BIT>
__device__ __forceinline__ void gate_bcast(u64* PX, u64* PY, float4 g) {
    const float a = g.x, b = g.y, c = g.z, d = g.w;
    const u64 A  = pk2(a, a);
    const u64 Bp = pk2(b, b),  Bn = pk2(-b, -b);
    const u64 Cp = pk2(c, c),  Cn = pk2(-c, -c);
    const u64 Dp = pk2(d, d),  Dn = pk2(-d, -d);
    #pragma unroll
    for (int j = 0; j < 16; j++) {
        if (j & (1 << BIT)) continue;
        const int j2 = j | (1 << BIT);
        u64 x0 = PX[j], y0 = PY[j], x1 = PX[j2], y1 = PY[j2];
        u64 r0x = fma2(A,  x0, fma2(Bn, y0, fma2(Cp, x1, mul2(Dn, y1))));
        u64 r0y = fma2(A,  y0, fma2(Bp, x0, fma2(Cp, y1, mul2(Dp, x1))));
        u64 r1x = fma2(Cn, x0, fma2(Dn, y0, fma2(A,  x1, mul2(Bp, y1))));
        u64 r1y = fma2(Cn, y0, fma2(Dp, x0, fma2(A,  y1, mul2(Bn, x1))));
        PX[j] = r0x; PY[j] = r0y; PX[j2] = r1x; PY[j2] = r1y;
    }
}

// Pair-form gate: butterfly partners are the two lanes of each packed element.
__device__ __forceinline__ void gate_pair(u64* PX, u64* PY, float4 g) {
    const float a = g.x, b = g.y, c = g.z, d = g.w;
    const u64 A   = pk2(a, a);
    const u64 Or  = pk2(c, -c);
    const u64 Di  = pk2(b, -b), Din = pk2(-b, b);
    const u64 Oi  = pk2(d, d),  Oin = pk2(-d, -d);
    #pragma unroll
    for (int j = 0; j < 16; j++) {
        u64 px = PX[j], py = PY[j];
        u64 sx = swap2(px), sy = swap2(py);
        u64 rx = fma2(A, px, fma2(Or, sx, fma2(Din, py, mul2(Oin, sy))));
        u64 ry = fma2(A, py, fma2(Or, sy, fma2(Di,  px, mul2(Oi,  sx))));
        PX[j] = rx; PY[j] = ry;
    }
}

// One CTA simulates one (batch, circuit) pair. State in two swizzled u64
// SMEM planes. Layer = 3 register passes; pass A uses store-where-you-read
// (gray slots) so it needs no CTA barrier, and A->B is intra-warp.
__global__ void __launch_bounds__(THREADS, 1)
pqc_kernel(const float* __restrict__ x,
           const float* __restrict__ qx1, const float* __restrict__ qz1,
           const float* __restrict__ c1,
           const float* __restrict__ qx2, const float* __restrict__ qz2,
           const float* __restrict__ c2,
           float* __restrict__ out, int B)
{
    extern __shared__ u64 dsm[];            // 2 * HALF u64 = 128 KB
    u64* SX = dsm;
    u64* SY = dsm + HALF;
    __shared__ float4 U4[NGATES];           // gate coefficients (a,b,c,d)
    __shared__ float  csh[NQ];
    __shared__ float  amp[NQ][2];
    __shared__ float  wsum[THREADS / 32];

    const int tid  = threadIdx.x;
    const int b    = blockIdx.x;
    const int circ = blockIdx.y;

    const float* qx = circ ? qx2 : qx1;
    const float* qz = circ ? qz2 : qz1;
    const float* cc = circ ? c2  : c1;

    if (tid < NGATES) {
        float ax = 0.5f * qx[tid];
        float az = 0.5f * qz[tid];
        float cxv = cosf(ax), sxv = sinf(ax);
        float pr  = cosf(az), pii = -sinf(az);   // pm = (pr,pii), pp = conj
        U4[tid] = make_float4(pr * cxv, pii * cxv, pii * sxv, -pr * sxv);
    }
    if (tid < NQ) {
        csh[tid] = cc[tid];
        float bit = (x[b * NQ + tid] > 0.0f) ? 1.0f : 0.0f;
        float th = 1.5707963705062866f * bit;    // 0.5f * float32(pi) * bit
        amp[tid][0] = cosf(th);
        amp[tid][1] = sinf(th);
    }
    __syncthreads();

    u64 PX[16], PY[16];
    float local = 0.0f;

    for (int l = 0; l <= NL; l++) {
        const int gb = l * NQ;

        // ===== Pass A: i bits 0..4, pairing on bit 0 (wires 13..9) =====
        // Gathers logical src s = gray(m) from canonical slot phys64(s), and
        // stores its result for m back into THE SAME slot phys64(gray(m)).
        // Read-set == write-set per thread -> no CTA barrier needed at all.
        if (l == 0) {
            float ph = 1.0f;
            #pragma unroll
            for (int w = 0; w < 9; w++)
                ph *= amp[w][(tid >> (8 - w)) & 1];
            const float a13_0 = amp[13][0], a13_1 = amp[13][1];
            #pragma unroll
            for (int j = 0; j < 16; j++) {
                float pj = ph;
                #pragma unroll
                for (int w = 9; w < 13; w++)
                    pj *= amp[w][(j >> (12 - w)) & 1];
                PX[j] = pk2(pj * a13_0, pj * a13_1);
                PY[j] = 0ULL;
            }
        } else {
            // fused CNOT-ladder (Gray) gather: dst 2m/2m+1 <- src (2m^m)^{0,1}
            #pragma unroll
            for (int j = 0; j < 16; j++) {
                int m  = (tid << 4) | j;
                int ps = m ^ (m >> 1);
                u64 vx = SX[phys64(ps)], vy = SY[phys64(ps)];
                if (j & 1) { vx = swap2(vx); vy = swap2(vy); }
                PX[j] = vx; PY[j] = vy;
            }
        }
        gate_pair(PX, PY, U4[gb + 13]);
        gate_bcast<0>(PX, PY, U4[gb + 12]);
        gate_bcast<1>(PX, PY, U4[gb + 11]);
        gate_bcast<2>(PX, PY, U4[gb + 10]);
        gate_bcast<3>(PX, PY, U4[gb + 9]);
        // store logical pair m (natural lane order) into gray slot
        #pragma unroll
        for (int j = 0; j < 16; j++) {
            int m  = (tid << 4) | j;
            int ps = m ^ (m >> 1);
            SX[phys64(ps)] = PX[j];
            SY[phys64(ps)] = PY[j];
        }
        __syncwarp();   // A->B exchange is intra-warp (producer tid_a has same hi4)

        // ===== Pass B: i bits 5..9, pairing on bit 5 (wires 8..4) =====
        // Loads from gray slots (A's layout), stores back CANONICAL layout.
        {
            const int hi4 = tid >> 5, lo5 = tid & 31, lane = lo5 & 1;
            const int lp  = lo5 >> 1;
            const float* fx = (const float*)SX;
            const float* fy = (const float*)SY;
            #pragma unroll
            for (int j = 0; j < 16; j++) {
                int p0 = (hi4 << 9) | (j << 5) | lp;
                int p1 = p0 | 16;
                int g0 = p0 ^ (p0 >> 1), g1 = p1 ^ (p1 >> 1);
                int a0 = 2 * phys64(g0) + lane, a1 = 2 * phys64(g1) + lane;
                PX[j] = pk2(fx[a0], fx[a1]);
                PY[j] = pk2(fy[a0], fy[a1]);
            }
            gate_pair(PX, PY, U4[gb + 8]);
            gate_bcast<0>(PX, PY, U4[gb + 7]);
            gate_bcast<1>(PX, PY, U4[gb + 6]);
            gate_bcast<2>(PX, PY, U4[gb + 5]);
            gate_bcast<3>(PX, PY, U4[gb + 4]);
            __syncthreads();    // WAR: all gray-slot loads done before canonical stores
            float* fxw = (float*)SX;
            float* fyw = (float*)SY;
            #pragma unroll
            for (int j = 0; j < 16; j++) {
                int p0 = (hi4 << 9) | (j << 5) | lp;
                int p1 = p0 | 16;
                int a0 = 2 * phys64(p0) + lane, a1 = 2 * phys64(p1) + lane;
                float xl, xh, yl, yh;
                upk2(PX[j], xl, xh); upk2(PY[j], yl, yh);
                fxw[a0] = xl; fxw[a1] = xh; fyw[a0] = yl; fyw[a1] = yh;
            }
            __syncthreads();    // RAW for pass C
        }

        // ===== Pass C: i bits {0,10..13}, canonical layout =====
        {
            #pragma unroll
            for (int j = 0; j < 16; j++) {
                int p = (j << 9) | tid;
                PX[j] = SX[phys64(p)]; PY[j] = SY[phys64(p)];
            }
            gate_bcast<0>(PX, PY, U4[gb + 3]);
            gate_bcast<1>(PX, PY, U4[gb + 2]);
            gate_bcast<2>(PX, PY, U4[gb + 1]);
            gate_bcast<3>(PX, PY, U4[gb + 0]);
            if (l < NL) {
                #pragma unroll
                for (int j = 0; j < 16; j++) {
                    int p = (j << 9) | tid;
                    SX[phys64(p)] = PX[j]; SY[phys64(p)] = PY[j];
                }
                __syncthreads();  // RAW for next layer's pass A gather
            } else {
                // Fused expectation. i = (j<<10) | (tid<<1) | lane.
                float gt = 0.0f;
                #pragma unroll
                for (int w = 4; w < 13; w++)
                    gt += ((tid >> (12 - w)) & 1) ? -csh[w] : csh[w];
                const float c13 = csh[13];
                #pragma unroll
                for (int j = 0; j < 16; j++) {
                    float gj = 0.0f;
                    #pragma unroll
                    for (int w = 0; w < 4; w++)
                        gj += ((j >> (3 - w)) & 1) ? -csh[w] : csh[w];
                    float x0, x1, y0, y1;
                    upk2(PX[j], x0, x1); upk2(PY[j], y0, y1);
                    local += (x0 * x0 + y0 * y0) * (gt + gj + c13)
                           + (x1 * x1 + y1 * y1) * (gt + gj - c13);
                }
            }
        }
    }

    // deterministic reduction
    #pragma unroll
    for (int off = 16; off; off >>= 1)
        local += __shfl_down_sync(0xffffffffu, local, off);
    if ((tid & 31) == 0) wsum[tid >> 5] = local;
    __syncthreads();
    if (tid == 0) {
        float tot = 0.0f;
        #pragma unroll
        for (int i = 0; i < THREADS / 32; i++) tot += wsum[i];
        // PLANAR complex output: out[0..B) = real (f1), out[B..2B) = imag (f2)
        out[circ * B + b] = tot;
    }
}

extern "C" void kernel_launch(void* const* d_in, const int* in_sizes, int n_in,
                              void* d_out, int out_size)
{
    const float *x, *qx1, *qz1, *c1, *qx2, *qz2, *c2;

    if (n_in >= 7 && in_sizes[0] > 1000) {
        // dict order: x, q_x1, q_z1, c1, q_x2, q_z2, c2
        x   = (const float*)d_in[0];
        qx1 = (const float*)d_in[1];
        qz1 = (const float*)d_in[2];
        c1  = (const float*)d_in[3];
        qx2 = (const float*)d_in[4];
        qz2 = (const float*)d_in[5];
        c2  = (const float*)d_in[6];
    } else if (n_in >= 7 && in_sizes[0] == NQ && in_sizes[1] == NQ) {
        c1  = (const float*)d_in[0];
        c2  = (const float*)d_in[1];
        qx1 = (const float*)d_in[2];
        qx2 = (const float*)d_in[3];
        qz1 = (const float*)d_in[4];
        qz2 = (const float*)d_in[5];
        x   = (const float*)d_in[6];
    } else {
        const float* qs[4] = {0, 0, 0, 0};
        const float* cs[2] = {0, 0};
        const float* xp = 0;
        int nq = 0, nc = 0;
        for (int i = 0; i < n_in; i++) {
            if (in_sizes[i] > 1000)         xp = (const float*)d_in[i];
            else if (in_sizes[i] == NGATES) { if (nq < 4) qs[nq++] = (const float*)d_in[i]; }
            else if (in_sizes[i] == NQ)     { if (nc < 2) cs[nc++] = (const float*)d_in[i]; }
        }
        x = xp; qx1 = qs[0]; qz1 = qs[1]; qx2 = qs[2]; qz2 = qs[3];
        c1 = cs[0]; c2 = cs[1];
    }

    int xsz = 0;
    for (int i = 0; i < n_in; i++) if (in_sizes[i] > xsz) xsz = in_sizes[i];
    const int B = xsz / NQ;  // 256

    cudaFuncSetAttribute(pqc_kernel,
                         cudaFuncAttributeMaxDynamicSharedMemorySize,
                         DIM * sizeof(u64));   // 128 KB (2 planes of HALF u64)

    dim3 grid(B, 2);
    pqc_kernel<<<grid, THREADS, DIM * sizeof(u64)>>>(
        x, qx1, qz1, c1, qx2, qz2, c2, (float*)d_out, B);
}

// round 10
// speedup vs baseline: 1.5659x; 1.5659x over previous
#include <cuda_runtime.h>

#define NQ      14
#define DIM     (1 << NQ)       // 16384 amplitudes
#define HALF    (DIM / 2)       // 8192 packed u64 per plane
#define NL      8
#define NGATES  ((NL + 1) * NQ) // 126 single-qubit gates
#define THREADS 512

typedef unsigned long long u64;

// XOR swizzle on u64-plane index; all passes use the same mapping.
__device__ __forceinline__ int phys64(int p) { return p ^ ((p >> 4) & 15); }

__device__ __forceinline__ u64 pk2(float lo, float hi) {
    u64 r; asm("mov.b64 %0, {%1,%2};" : "=l"(r) : "f"(lo), "f"(hi)); return r;
}
__device__ __forceinline__ void upk2(u64 v, float& lo, float& hi) {
    asm("mov.b64 {%0,%1}, %2;" : "=f"(lo), "=f"(hi) : "l"(v));
}
__device__ __forceinline__ u64 swap2(u64 v) {
    float lo, hi; upk2(v, lo, hi); return pk2(hi, lo);
}
__device__ __forceinline__ u64 fma2(u64 a, u64 b, u64 c) {
    u64 d; asm("fma.rn.f32x2 %0, %1, %2, %3;" : "=l"(d) : "l"(a), "l"(b), "l"(c));
    return d;
}
__device__ __forceinline__ u64 mul2(u64 a, u64 b) {
    u64 d; asm("mul.rn.f32x2 %0, %1, %2;" : "=l"(d) : "l"(a), "l"(b));
    return d;
}

// ---- Rx-only butterflies (real coefficients: cx = cos(qx/2), sx = sin(qx/2))
// new0 = cx*a0 - i sx*a1 : re = cx*x0 + sx*y1 ; im = cx*y0 - sx*x1
// new1 = -i sx*a0 + cx*a1: re = sx*y0 + cx*x1 ; im = -sx*x0 + cx*y1

// Broadcast: butterfly partners are distinct packed elements (bit BIT of j).
template<int BIT>
__device__ __forceinline__ void rx_bcast(u64* PX, u64* PY, float2 g) {
    const u64 C  = pk2(g.x,  g.x);
    const u64 Sp = pk2(g.y,  g.y);
    const u64 Sn = pk2(-g.y, -g.y);
    #pragma unroll
    for (int j = 0; j < 16; j++) {
        if (j & (1 << BIT)) continue;
        const int j2 = j | (1 << BIT);
        u64 x0 = PX[j], y0 = PY[j], x1 = PX[j2], y1 = PY[j2];
        PX[j]  = fma2(C, x0, mul2(Sp, y1));
        PY[j]  = fma2(C, y0, mul2(Sn, x1));
        PX[j2] = fma2(C, x1, mul2(Sp, y0));
        PY[j2] = fma2(C, y1, mul2(Sn, x0));
    }
}

// Pair-form: butterfly partners are the two lanes of each packed element.
__device__ __forceinline__ void rx_pair(u64* PX, u64* PY, float2 g) {
    const u64 C  = pk2(g.x,  g.x);
    const u64 Sp = pk2(g.y,  g.y);
    const u64 Sn = pk2(-g.y, -g.y);
    #pragma unroll
    for (int j = 0; j < 16; j++) {
        u64 px = PX[j], py = PY[j];
        u64 sxw = swap2(px), syw = swap2(py);
        PX[j] = fma2(C, px, mul2(Sp, syw));  // lane0: cx*x0+sx*y1 ; lane1: cx*x1+sx*y0
        PY[j] = fma2(C, py, mul2(Sn, sxw));  // lane0: cx*y0-sx*x1 ; lane1: cx*y1-sx*x0
    }
}

// One CTA simulates one (batch, circuit) pair. State in two swizzled u64 SMEM
// planes. Layer = (prev Gray perm) + 14 Rx butterflies in 3 register passes +
// one global diagonal Rz phase (merged across all 14 wires, skipped in the
// last layer since it cannot change probabilities).
__global__ void __launch_bounds__(THREADS, 1)
pqc_kernel(const float* __restrict__ x,
           const float* __restrict__ qx1, const float* __restrict__ qz1,
           const float* __restrict__ c1,
           const float* __restrict__ qx2, const float* __restrict__ qz2,
           const float* __restrict__ c2,
           float* __restrict__ out, int B)
{
    extern __shared__ u64 dsm[];            // 2 * HALF u64 = 128 KB
    u64* SX = dsm;
    u64* SY = dsm + HALF;
    __shared__ float2 U2[NGATES];           // (cos(qx/2), sin(qx/2)) per gate
    __shared__ float  qzh[NGATES];          // qz/2 per gate
    __shared__ float2 ejt[16];              // per-layer j-part phase table
    __shared__ float  csh[NQ];
    __shared__ float  amp[NQ][2];
    __shared__ float  wsum[THREADS / 32];

    const int tid  = threadIdx.x;
    const int b    = blockIdx.x;
    const int circ = blockIdx.y;

    const float* qx = circ ? qx2 : qx1;
    const float* qz = circ ? qz2 : qz1;
    const float* cc = circ ? c2  : c1;

    if (tid < NGATES) {
        float ax = 0.5f * qx[tid];
        U2[tid]  = make_float2(cosf(ax), sinf(ax));
        qzh[tid] = 0.5f * qz[tid];
    }
    if (tid < NQ) {
        csh[tid] = cc[tid];
        float bit = (x[b * NQ + tid] > 0.0f) ? 1.0f : 0.0f;
        float th = 1.5707963705062866f * bit;    // 0.5f * float32(pi) * bit
        amp[tid][0] = cosf(th);
        amp[tid][1] = sinf(th);
    }
    __syncthreads();

    u64 PX[16], PY[16];
    float local = 0.0f;

    for (int l = 0; l <= NL; l++) {
        const int gb = l * NQ;

        // ===== Pass A: i bits 0..4, pairing on bit 0 (wires 13..9) =====
        if (l == 0) {
            float ph = 1.0f;
            #pragma unroll
            for (int w = 0; w < 9; w++)
                ph *= amp[w][(tid >> (8 - w)) & 1];
            const float a13_0 = amp[13][0], a13_1 = amp[13][1];
            #pragma unroll
            for (int j = 0; j < 16; j++) {
                float pj = ph;
                #pragma unroll
                for (int w = 9; w < 13; w++)
                    pj *= amp[w][(j >> (12 - w)) & 1];
                PX[j] = pk2(pj * a13_0, pj * a13_1);
                PY[j] = 0ULL;
            }
        } else {
            // fused CNOT-ladder (Gray) gather: dst 2m/2m+1 <- src (2m^m)^{0,1}
            #pragma unroll
            for (int j = 0; j < 16; j++) {
                int m  = (tid << 4) | j;
                int ps = m ^ (m >> 1);
                u64 vx = SX[phys64(ps)], vy = SY[phys64(ps)];
                if (j & 1) { vx = swap2(vx); vy = swap2(vy); }
                PX[j] = vx; PY[j] = vy;
            }
        }
        rx_pair(PX, PY, U2[gb + 13]);
        rx_bcast<0>(PX, PY, U2[gb + 12]);
        rx_bcast<1>(PX, PY, U2[gb + 11]);
        rx_bcast<2>(PX, PY, U2[gb + 10]);
        rx_bcast<3>(PX, PY, U2[gb + 9]);
        if (l > 0) __syncthreads();         // WAR: all gathers read first
        #pragma unroll
        for (int j = 0; j < 16; j++) {
            int p = (tid << 4) | j;
            SX[phys64(p)] = PX[j]; SY[phys64(p)] = PY[j];
        }
        __syncthreads();

        // ===== Pass B: i bits 5..9, pairing on bit 5 (wires 8..4) =====
        {
            const int hi4 = tid >> 5, lo5 = tid & 31, lane = lo5 & 1;
            const int lp  = lo5 >> 1;
            const float* fx = (const float*)SX;
            const float* fy = (const float*)SY;
            #pragma unroll
            for (int j = 0; j < 16; j++) {
                int p0 = (hi4 << 9) | (j << 5) | lp;
                int p1 = p0 | 16;
                int a0 = 2 * phys64(p0) + lane, a1 = 2 * phys64(p1) + lane;
                PX[j] = pk2(fx[a0], fx[a1]);
                PY[j] = pk2(fy[a0], fy[a1]);
            }
            rx_pair(PX, PY, U2[gb + 8]);
            rx_bcast<0>(PX, PY, U2[gb + 7]);
            rx_bcast<1>(PX, PY, U2[gb + 6]);
            rx_bcast<2>(PX, PY, U2[gb + 5]);
            rx_bcast<3>(PX, PY, U2[gb + 4]);
            __syncthreads();    // WAR
            float* fxw = (float*)SX;
            float* fyw = (float*)SY;
            #pragma unroll
            for (int j = 0; j < 16; j++) {
                int p0 = (hi4 << 9) | (j << 5) | lp;
                int p1 = p0 | 16;
                int a0 = 2 * phys64(p0) + lane, a1 = 2 * phys64(p1) + lane;
                float xl, xh, yl, yh;
                upk2(PX[j], xl, xh); upk2(PY[j], yl, yh);
                fxw[a0] = xl; fxw[a1] = xh; fyw[a0] = yl; fyw[a1] = yh;
            }
            // per-layer j-part phase table for the merged Rz diagonal
            // (wires 0..3 <-> i bits 13..10 <-> pass-C j bits 3..0)
            if (l < NL && tid < 16) {
                float a = 0.0f;
                #pragma unroll
                for (int w = 0; w < 4; w++)
                    a += ((tid >> (3 - w)) & 1) ? qzh[gb + w] : -qzh[gb + w];
                ejt[tid] = make_float2(cosf(a), sinf(a));
            }
            __syncthreads();    // RAW for pass C (state + table)
        }

        // ===== Pass C: i bits {0,10..13}, canonical layout =====
        {
            #pragma unroll
            for (int j = 0; j < 16; j++) {
                int p = (j << 9) | tid;
                PX[j] = SX[phys64(p)]; PY[j] = SY[phys64(p)];
            }
            rx_bcast<0>(PX, PY, U2[gb + 3]);
            rx_bcast<1>(PX, PY, U2[gb + 2]);
            rx_bcast<2>(PX, PY, U2[gb + 1]);
            rx_bcast<3>(PX, PY, U2[gb + 0]);

            if (l < NL) {
                // Merged Rz diagonal: phase(i) = exp(i * sum_w (+/-) qz_w/2).
                // i = (j<<10) | (tid<<1) | lane. tid bits 8..0 <-> wires 4..12,
                // lane <-> wire 13, j bits 3..0 <-> wires 0..3.
                float pht = 0.0f;
                #pragma unroll
                for (int w = 4; w < 13; w++)
                    pht += ((tid >> (12 - w)) & 1) ? qzh[gb + w] : -qzh[gb + w];
                const float z13 = qzh[gb + 13];
                const float a0 = pht - z13, a1 = pht + z13;
                const u64 Er = pk2(cosf(a0), cosf(a1));
                const u64 Ei = pk2(sinf(a0), sinf(a1));
                #pragma unroll
                for (int j = 0; j < 16; j++) {
                    const float ejr = ejt[j].x, eji = ejt[j].y;
                    const u64 EJR  = pk2(ejr,  ejr);
                    const u64 EJRn = pk2(-ejr, -ejr);
                    const u64 EJIp = pk2(eji,  eji);
                    const u64 EJIn = pk2(-eji, -eji);
                    u64 Pr  = fma2(EJR,  Er, mul2(EJIn, Ei));  //  ejr*Er - eji*Ei
                    u64 Pi  = fma2(EJR,  Ei, mul2(EJIp, Er));  //  ejr*Ei + eji*Er
                    u64 Pin = fma2(EJRn, Ei, mul2(EJIn, Er));  // -(Pi)
                    u64 nx = fma2(PX[j], Pr, mul2(PY[j], Pin));
                    u64 ny = fma2(PY[j], Pr, mul2(PX[j], Pi));
                    PX[j] = nx; PY[j] = ny;
                }
                #pragma unroll
                for (int j = 0; j < 16; j++) {
                    int p = (j << 9) | tid;
                    SX[phys64(p)] = PX[j]; SY[phys64(p)] = PY[j];
                }
                __syncthreads();  // RAW for next layer's pass A gather
            } else {
                // Last layer: merged diagonal is a pure phase -> skip it.
                // Fused expectation. i = (j<<10) | (tid<<1) | lane.
                float gt = 0.0f;
                #pragma unroll
                for (int w = 4; w < 13; w++)
                    gt += ((tid >> (12 - w)) & 1) ? -csh[w] : csh[w];
                const float c13 = csh[13];
                #pragma unroll
                for (int j = 0; j < 16; j++) {
                    float gj = 0.0f;
                    #pragma unroll
                    for (int w = 0; w < 4; w++)
                        gj += ((j >> (3 - w)) & 1) ? -csh[w] : csh[w];
                    float x0, x1, y0, y1;
                    upk2(PX[j], x0, x1); upk2(PY[j], y0, y1);
                    local += (x0 * x0 + y0 * y0) * (gt + gj + c13)
                           + (x1 * x1 + y1 * y1) * (gt + gj - c13);
                }
            }
        }
    }

    // deterministic reduction
    #pragma unroll
    for (int off = 16; off; off >>= 1)
        local += __shfl_down_sync(0xffffffffu, local, off);
    if ((tid & 31) == 0) wsum[tid >> 5] = local;
    __syncthreads();
    if (tid == 0) {
        float tot = 0.0f;
        #pragma unroll
        for (int i = 0; i < THREADS / 32; i++) tot += wsum[i];
        // PLANAR complex output: out[0..B) = real (f1), out[B..2B) = imag (f2)
        out[circ * B + b] = tot;
    }
}

extern "C" void kernel_launch(void* const* d_in, const int* in_sizes, int n_in,
                              void* d_out, int out_size)
{
    const float *x, *qx1, *qz1, *c1, *qx2, *qz2, *c2;

    if (n_in >= 7 && in_sizes[0] > 1000) {
        // dict order: x, q_x1, q_z1, c1, q_x2, q_z2, c2
        x   = (const float*)d_in[0];
        qx1 = (const float*)d_in[1];
        qz1 = (const float*)d_in[2];
        c1  = (const float*)d_in[3];
        qx2 = (const float*)d_in[4];
        qz2 = (const float*)d_in[5];
        c2  = (const float*)d_in[6];
    } else if (n_in >= 7 && in_sizes[0] == NQ && in_sizes[1] == NQ) {
        c1  = (const float*)d_in[0];
        c2  = (const float*)d_in[1];
        qx1 = (const float*)d_in[2];
        qx2 = (const float*)d_in[3];
        qz1 = (const float*)d_in[4];
        qz2 = (const float*)d_in[5];
        x   = (const float*)d_in[6];
    } else {
        const float* qs[4] = {0, 0, 0, 0};
        const float* cs[2] = {0, 0};
        const float* xp = 0;
        int nq = 0, nc = 0;
        for (int i = 0; i < n_in; i++) {
            if (in_sizes[i] > 1000)         xp = (const float*)d_in[i];
            else if (in_sizes[i] == NGATES) { if (nq < 4) qs[nq++] = (const float*)d_in[i]; }
            else if (in_sizes[i] == NQ)     { if (nc < 2) cs[nc++] = (const float*)d_in[i]; }
        }
        x = xp; qx1 = qs[0]; qz1 = qs[1]; qx2 = qs[2]; qz2 = qs[3];
        c1 = cs[0]; c2 = cs[1];
    }

    int xsz = 0;
    for (int i = 0; i < n_in; i++) if (in_sizes[i] > xsz) xsz = in_sizes[i];
    const int B = xsz / NQ;  // 256

    cudaFuncSetAttribute(pqc_kernel,
                         cudaFuncAttributeMaxDynamicSharedMemorySize,
                         DIM * sizeof(u64));   // 128 KB (2 planes of HALF u64)

    dim3 grid(B, 2);
    pqc_kernel<<<grid, THREADS, DIM * sizeof(u64)>>>(
        x, qx1, qz1, c1, qx2, qz2, c2, (float*)d_out, B);
}